// round 2
// baseline (speedup 1.0000x reference)
#include <cuda_runtime.h>
#include <cstdint>

// SGConv K=2: h = P (P x), P = D^-1/2 (A + I) D^-1/2, deg over dst (+ self loop).
// CSR (by dst) built per launch; per-edge payload packed as int2{src, coef}.
// Hops: one warp per node, 3 accumulators/lane, 4-edge unroll. Features (19.2MB)
// are L2-resident -> hops run at the L2 bandwidth roofline, no atomics.

#define N_NODES 50000
#define N_EDGES 800000
#define N_FEAT  96

// ---------------- device scratch (allocation-free rule: __device__ globals) ----
__device__ int   g_is64;                    // 1 if edge_index is int64, 0 if int32
__device__ int   g_counts[N_NODES];         // in-degree (dst)
__device__ int   g_cursor[N_NODES];         // scatter cursors
__device__ int   g_rowptr[N_NODES + 1];     // CSR row pointers (by dst)
__device__ float g_dis[N_NODES];            // (deg+1)^-1/2
__device__ int2  g_edge[N_EDGES];           // packed {src, __float_as_int(coef)}
__device__ float g_tmp[(size_t)N_NODES * N_FEAT]; // hop-1 output

// ---------------- dtype detection ---------------------------------------------
// Values in [0, 50000). int64 little-endian => every odd 32-bit word is 0.
// int32 => odd words ~uniform in [0,50000): P(all 2048 samples zero) ~ 0.
__global__ void detect_kernel(const void* ei) {
    __shared__ int nz;
    if (threadIdx.x == 0) nz = 0;
    __syncthreads();
    const int* w = (const int*)ei;
    int local = 0;
    for (int i = threadIdx.x; i < 2048; i += blockDim.x)
        if (w[2 * i + 1] != 0) local = 1;
    if (local) atomicExch(&nz, 1);
    __syncthreads();
    if (threadIdx.x == 0) g_is64 = (nz == 0) ? 1 : 0;
}

__device__ __forceinline__ int edge_src(const void* ei, int e) {
    if (g_is64) return (int)((const long long*)ei)[e];
    return ((const int*)ei)[e];
}
__device__ __forceinline__ int edge_dst(const void* ei, int e) {
    if (g_is64) return (int)((const long long*)ei)[N_EDGES + e];
    return ((const int*)ei)[N_EDGES + e];
}

// ---------------- degree --------------------------------------------------------
__global__ void degree_kernel(const void* __restrict__ ei) {
    int e = blockIdx.x * blockDim.x + threadIdx.x;
    if (e < N_EDGES) atomicAdd(&g_counts[edge_dst(ei, e)], 1);
}

// ---------------- fused scan (rowptr) + dis -------------------------------------
// 1 block, 1024 threads. Each thread serially owns ITEMS contiguous counts:
// local sum -> one block-wide scan -> re-walk writing rowptr. ~6 barriers total.
__global__ void __launch_bounds__(1024) scan_dis_kernel() {
    const int ITEMS = (N_NODES + 1023) / 1024;   // 49
    const int tid = threadIdx.x, lane = tid & 31, wid = tid >> 5;
    const int base = tid * ITEMS;

    // phase 1: local sums + dis
    int s = 0;
    #pragma unroll 4
    for (int j = 0; j < ITEMS; j++) {
        int i = base + j;
        if (i < N_NODES) {
            int c = g_counts[i];
            s += c;
            g_dis[i] = rsqrtf((float)(c + 1));   // +1 self loop
        }
    }

    // phase 2: block exclusive scan over the 1024 local sums
    __shared__ int wsum[32];
    int incl = s;
    #pragma unroll
    for (int off = 1; off < 32; off <<= 1) {
        int t = __shfl_up_sync(0xFFFFFFFFu, incl, off);
        if (lane >= off) incl += t;
    }
    if (lane == 31) wsum[wid] = incl;
    __syncthreads();
    if (wid == 0) {
        int v = wsum[lane];
        #pragma unroll
        for (int off = 1; off < 32; off <<= 1) {
            int t = __shfl_up_sync(0xFFFFFFFFu, v, off);
            if (lane >= off) v += t;
        }
        wsum[lane] = v;
    }
    __syncthreads();
    int excl = incl - s + (wid > 0 ? wsum[wid - 1] : 0);

    // phase 3: write rowptr (counts hot in L1/L2)
    if (tid == 0) g_rowptr[0] = 0;
    int run = excl;
    #pragma unroll 4
    for (int j = 0; j < ITEMS; j++) {
        int i = base + j;
        if (i < N_NODES) {
            run += g_counts[i];
            g_rowptr[i + 1] = run;
        }
    }
}

// ---------------- scatter: one packed 8B store per edge -------------------------
__global__ void scatter_kernel(const void* __restrict__ ei) {
    int e = blockIdx.x * blockDim.x + threadIdx.x;
    if (e >= N_EDGES) return;
    int s = edge_src(ei, e);
    int d = edge_dst(ei, e);
    int pos = g_rowptr[d] + atomicAdd(&g_cursor[d], 1);
    float coef = g_dis[s] * g_dis[d];
    g_edge[pos] = make_int2(s, __float_as_int(coef));
}

// ---------------- hop: one warp per node, 3 accumulators, 4-edge unroll ---------
__global__ void __launch_bounds__(256) hop_kernel(const float* __restrict__ hin,
                                                  float* __restrict__ hout) {
    const int node = blockIdx.x * (blockDim.x >> 5) + (threadIdx.x >> 5);
    if (node >= N_NODES) return;
    const int lane = threadIdx.x & 31;

    // self-loop: dis[node]^2 * h[node]
    float sc = g_dis[node];
    sc = sc * sc;
    const float* hn = hin + (size_t)node * N_FEAT;
    float a0 = sc * hn[lane];
    float a1 = sc * hn[lane + 32];
    float a2 = sc * hn[lane + 64];

    int e = g_rowptr[node];
    const int end = g_rowptr[node + 1];

    for (; e + 3 < end; e += 4) {
        int2 p0 = g_edge[e];
        int2 p1 = g_edge[e + 1];
        int2 p2 = g_edge[e + 2];
        int2 p3 = g_edge[e + 3];
        const float* h0 = hin + (size_t)p0.x * N_FEAT;
        const float* h1 = hin + (size_t)p1.x * N_FEAT;
        const float* h2 = hin + (size_t)p2.x * N_FEAT;
        const float* h3 = hin + (size_t)p3.x * N_FEAT;
        float c0 = __int_as_float(p0.y), c1 = __int_as_float(p1.y);
        float c2 = __int_as_float(p2.y), c3 = __int_as_float(p3.y);
        float x00 = h0[lane], x01 = h0[lane + 32], x02 = h0[lane + 64];
        float x10 = h1[lane], x11 = h1[lane + 32], x12 = h1[lane + 64];
        float x20 = h2[lane], x21 = h2[lane + 32], x22 = h2[lane + 64];
        float x30 = h3[lane], x31 = h3[lane + 32], x32 = h3[lane + 64];
        a0 += c0 * x00; a1 += c0 * x01; a2 += c0 * x02;
        a0 += c1 * x10; a1 += c1 * x11; a2 += c1 * x12;
        a0 += c2 * x20; a1 += c2 * x21; a2 += c2 * x22;
        a0 += c3 * x30; a1 += c3 * x31; a2 += c3 * x32;
    }
    for (; e < end; e++) {
        int2 p = g_edge[e];
        const float* hs = hin + (size_t)p.x * N_FEAT;
        float c = __int_as_float(p.y);
        a0 += c * hs[lane]; a1 += c * hs[lane + 32]; a2 += c * hs[lane + 64];
    }

    float* ho = hout + (size_t)node * N_FEAT;
    ho[lane] = a0; ho[lane + 32] = a1; ho[lane + 64] = a2;
}

// ---------------- launch --------------------------------------------------------
extern "C" void kernel_launch(void* const* d_in, const int* in_sizes, int n_in,
                              void* d_out, int out_size) {
    const float* x  = (const float*)d_in[0];
    const void*  ei = d_in[1];
    float* out = (float*)d_out;

    float* tmp = nullptr; int* cnt = nullptr; int* cur = nullptr;
    cudaGetSymbolAddress((void**)&tmp, g_tmp);
    cudaGetSymbolAddress((void**)&cnt, g_counts);
    cudaGetSymbolAddress((void**)&cur, g_cursor);

    const int TB = 256;
    cudaMemsetAsync(cnt, 0, N_NODES * sizeof(int));
    cudaMemsetAsync(cur, 0, N_NODES * sizeof(int));
    detect_kernel<<<1, 256>>>(ei);
    degree_kernel<<<(N_EDGES + TB - 1) / TB, TB>>>(ei);
    scan_dis_kernel<<<1, 1024>>>();
    scatter_kernel<<<(N_EDGES + TB - 1) / TB, TB>>>(ei);

    const int warps_per_block = TB / 32;
    const int hop_grid = (N_NODES + warps_per_block - 1) / warps_per_block;
    hop_kernel<<<hop_grid, TB>>>(x, tmp);
    hop_kernel<<<hop_grid, TB>>>(tmp, out);
}

// round 3
// speedup vs baseline: 1.8553x; 1.8553x over previous
#include <cuda_runtime.h>
#include <cstdint>

// SGConv K=2: h = P (P x), P = D^-1/2 (A + I) D^-1/2, deg over dst (+ self loop).
// CSR (by dst) built per launch: degree (atomics) -> coalesced 2-kernel scan
// (block sums, then per-chunk block scan; also seeds scatter cursors) ->
// scatter (cursor atomics, packed int2{src,coef} payload).
// Hops: one warp per node, 3 accumulators/lane, 4-edge unroll; features (19.2MB)
// are L2-resident -> hops run at the L2 bandwidth roofline, no atomics.

#define N_NODES 50000
#define N_EDGES 800000
#define N_FEAT  96
#define SCAN_B  1024
#define N_CHUNK ((N_NODES + SCAN_B - 1) / SCAN_B)   // 49

// ---------------- device scratch (allocation-free rule: __device__ globals) ----
__device__ int   g_is64;                    // 1 if edge_index is int64, 0 if int32
__device__ int   g_counts[N_NODES];         // in-degree (dst)
__device__ int   g_cursor[N_NODES];         // scatter cursors (seeded = excl prefix)
__device__ int   g_rowptr[N_NODES + 1];     // CSR row pointers (by dst)
__device__ int   g_bsum[N_CHUNK];           // per-chunk sums
__device__ float g_dis[N_NODES];            // (deg+1)^-1/2
__device__ int2  g_edge[N_EDGES];           // packed {src, __float_as_int(coef)}
__device__ float g_tmp[(size_t)N_NODES * N_FEAT]; // hop-1 output

// ---------------- dtype detection ---------------------------------------------
// Values in [0, 50000). int64 little-endian => every odd 32-bit word is 0.
// int32 => odd words ~uniform in [0,50000): P(all 2048 samples zero) ~ 0.
__global__ void detect_kernel(const void* ei) {
    __shared__ int nz;
    if (threadIdx.x == 0) nz = 0;
    __syncthreads();
    const int* w = (const int*)ei;
    int local = 0;
    for (int i = threadIdx.x; i < 2048; i += blockDim.x)
        if (w[2 * i + 1] != 0) local = 1;
    if (local) atomicExch(&nz, 1);
    __syncthreads();
    if (threadIdx.x == 0) g_is64 = (nz == 0) ? 1 : 0;
}

__device__ __forceinline__ int edge_src(const void* ei, int e) {
    if (g_is64) return (int)((const long long*)ei)[e];
    return ((const int*)ei)[e];
}
__device__ __forceinline__ int edge_dst(const void* ei, int e) {
    if (g_is64) return (int)((const long long*)ei)[N_EDGES + e];
    return ((const int*)ei)[N_EDGES + e];
}

// ---------------- degree --------------------------------------------------------
__global__ void degree_kernel(const void* __restrict__ ei) {
    int e = blockIdx.x * blockDim.x + threadIdx.x;
    if (e < N_EDGES) atomicAdd(&g_counts[edge_dst(ei, e)], 1);
}

// ---------------- scan pass 1: coalesced chunk sums + dis -----------------------
__global__ void __launch_bounds__(SCAN_B) reduce_dis_kernel() {
    const int tid = threadIdx.x, lane = tid & 31, wid = tid >> 5;
    const int i = blockIdx.x * SCAN_B + tid;
    int c = 0;
    if (i < N_NODES) {
        c = g_counts[i];
        g_dis[i] = rsqrtf((float)(c + 1));   // +1 self loop
    }
    // block reduce
    __shared__ int wsum[32];
    int v = c;
    #pragma unroll
    for (int off = 16; off > 0; off >>= 1) v += __shfl_down_sync(0xFFFFFFFFu, v, off);
    if (lane == 0) wsum[wid] = v;
    __syncthreads();
    if (wid == 0) {
        int s = wsum[lane];
        #pragma unroll
        for (int off = 16; off > 0; off >>= 1) s += __shfl_down_sync(0xFFFFFFFFu, s, off);
        if (lane == 0) g_bsum[blockIdx.x] = s;
    }
}

// ---------------- scan pass 2: per-chunk coalesced block scan -------------------
// Each block computes its chunk offset from g_bsum, scans its 1024 counts, writes
// rowptr[i+1] (inclusive) and seeds g_cursor[i] with the exclusive prefix.
__global__ void __launch_bounds__(SCAN_B) scan_write_kernel() {
    const int tid = threadIdx.x, lane = tid & 31, wid = tid >> 5;
    const int i = blockIdx.x * SCAN_B + tid;

    // chunk offset = sum of bsum[0 .. blockIdx-1] (64-thread reduce)
    __shared__ int s_off[2];
    if (tid < 64) {
        int v = (tid < blockIdx.x && tid < N_CHUNK) ? g_bsum[tid] : 0;
        #pragma unroll
        for (int off = 16; off > 0; off >>= 1) v += __shfl_down_sync(0xFFFFFFFFu, v, off);
        if ((tid & 31) == 0) s_off[tid >> 5] = v;
    }

    int c = (i < N_NODES) ? g_counts[i] : 0;

    // block inclusive scan
    __shared__ int wsum[32];
    int incl = c;
    #pragma unroll
    for (int off = 1; off < 32; off <<= 1) {
        int t = __shfl_up_sync(0xFFFFFFFFu, incl, off);
        if (lane >= off) incl += t;
    }
    if (lane == 31) wsum[wid] = incl;
    __syncthreads();
    if (wid == 0) {
        int v = wsum[lane];
        #pragma unroll
        for (int off = 1; off < 32; off <<= 1) {
            int t = __shfl_up_sync(0xFFFFFFFFu, v, off);
            if (lane >= off) v += t;
        }
        wsum[lane] = v;
    }
    __syncthreads();

    int offset = s_off[0] + s_off[1] + (wid > 0 ? wsum[wid - 1] : 0);
    if (i < N_NODES) {
        int inc_total = offset + incl;
        g_rowptr[i + 1] = inc_total;
        g_cursor[i]     = inc_total - c;   // exclusive prefix = row start
    }
    if (blockIdx.x == 0 && tid == 0) g_rowptr[0] = 0;
}

// ---------------- scatter: cursor atomic + one packed 8B store per edge ---------
__global__ void scatter_kernel(const void* __restrict__ ei) {
    int e = blockIdx.x * blockDim.x + threadIdx.x;
    if (e >= N_EDGES) return;
    int s = edge_src(ei, e);
    int d = edge_dst(ei, e);
    int pos = atomicAdd(&g_cursor[d], 1);
    float coef = g_dis[s] * g_dis[d];
    g_edge[pos] = make_int2(s, __float_as_int(coef));
}

// ---------------- hop: one warp per node, 3 accumulators, 4-edge unroll ---------
__global__ void __launch_bounds__(256) hop_kernel(const float* __restrict__ hin,
                                                  float* __restrict__ hout) {
    const int node = blockIdx.x * (blockDim.x >> 5) + (threadIdx.x >> 5);
    if (node >= N_NODES) return;
    const int lane = threadIdx.x & 31;

    // self-loop: dis[node]^2 * h[node]
    float sc = g_dis[node];
    sc = sc * sc;
    const float* hn = hin + (size_t)node * N_FEAT;
    float a0 = sc * hn[lane];
    float a1 = sc * hn[lane + 32];
    float a2 = sc * hn[lane + 64];

    int e = g_rowptr[node];
    const int end = g_rowptr[node + 1];

    for (; e + 3 < end; e += 4) {
        int2 p0 = g_edge[e];
        int2 p1 = g_edge[e + 1];
        int2 p2 = g_edge[e + 2];
        int2 p3 = g_edge[e + 3];
        const float* h0 = hin + (size_t)p0.x * N_FEAT;
        const float* h1 = hin + (size_t)p1.x * N_FEAT;
        const float* h2 = hin + (size_t)p2.x * N_FEAT;
        const float* h3 = hin + (size_t)p3.x * N_FEAT;
        float c0 = __int_as_float(p0.y), c1 = __int_as_float(p1.y);
        float c2 = __int_as_float(p2.y), c3 = __int_as_float(p3.y);
        float x00 = h0[lane], x01 = h0[lane + 32], x02 = h0[lane + 64];
        float x10 = h1[lane], x11 = h1[lane + 32], x12 = h1[lane + 64];
        float x20 = h2[lane], x21 = h2[lane + 32], x22 = h2[lane + 64];
        float x30 = h3[lane], x31 = h3[lane + 32], x32 = h3[lane + 64];
        a0 += c0 * x00; a1 += c0 * x01; a2 += c0 * x02;
        a0 += c1 * x10; a1 += c1 * x11; a2 += c1 * x12;
        a0 += c2 * x20; a1 += c2 * x21; a2 += c2 * x22;
        a0 += c3 * x30; a1 += c3 * x31; a2 += c3 * x32;
    }
    for (; e < end; e++) {
        int2 p = g_edge[e];
        const float* hs = hin + (size_t)p.x * N_FEAT;
        float c = __int_as_float(p.y);
        a0 += c * hs[lane]; a1 += c * hs[lane + 32]; a2 += c * hs[lane + 64];
    }

    float* ho = hout + (size_t)node * N_FEAT;
    ho[lane] = a0; ho[lane + 32] = a1; ho[lane + 64] = a2;
}

// ---------------- launch --------------------------------------------------------
extern "C" void kernel_launch(void* const* d_in, const int* in_sizes, int n_in,
                              void* d_out, int out_size) {
    const float* x  = (const float*)d_in[0];
    const void*  ei = d_in[1];
    float* out = (float*)d_out;

    float* tmp = nullptr; int* cnt = nullptr;
    cudaGetSymbolAddress((void**)&tmp, g_tmp);
    cudaGetSymbolAddress((void**)&cnt, g_counts);

    const int TB = 256;
    cudaMemsetAsync(cnt, 0, N_NODES * sizeof(int));
    detect_kernel<<<1, 256>>>(ei);
    degree_kernel<<<(N_EDGES + TB - 1) / TB, TB>>>(ei);
    reduce_dis_kernel<<<N_CHUNK, SCAN_B>>>();
    scan_write_kernel<<<N_CHUNK, SCAN_B>>>();
    scatter_kernel<<<(N_EDGES + TB - 1) / TB, TB>>>(ei);

    const int warps_per_block = TB / 32;
    const int hop_grid = (N_NODES + warps_per_block - 1) / warps_per_block;
    hop_kernel<<<hop_grid, TB>>>(x, tmp);
    hop_kernel<<<hop_grid, TB>>>(tmp, out);
}